// round 1
// baseline (speedup 1.0000x reference)
#include <cuda_runtime.h>
#include <math_constants.h>

// Problem constants (fixed by the reference setup_inputs)
#define N_SRC 8192
#define M_TGT 32768
#define D_DIM 64
#define MSPLIT 16          // split M across CTAs for parallelism
#define M_PER_SPLIT (M_TGT / MSPLIT)   // 2048

#define BN 128             // source rows per CTA
#define BM 128             // target cols per main-loop tile
#define TN 8               // rows per thread
#define TM 8               // cols per thread
#define THREADS ((BN / TN) * (BM / TM))   // 256

// -------- device scratch (no allocations allowed) --------
__device__ float g_srcT[D_DIM * N_SRC];     // k-major source: [d][n]
__device__ float g_tgtT[D_DIM * M_TGT];     // k-major target: [d][m]
__device__ float g_c[M_TGT];                // ||y_m||^2 - psi[m]
__device__ float g_sqsrc[N_SRC];            // ||x_n||^2
__device__ float g_meanpsi;
__device__ float g_partial[N_SRC * MSPLIT]; // partial mins

// ---------------------------------------------------------
// Prep: transpose source to k-major + row norms
// ---------------------------------------------------------
__global__ void prep_src_kernel(const float* __restrict__ src) {
    int n = blockIdx.x * blockDim.x + threadIdx.x;
    if (n >= N_SRC) return;
    float s = 0.f;
#pragma unroll
    for (int d = 0; d < D_DIM; d++) {
        float v = src[n * D_DIM + d];
        g_srcT[d * N_SRC + n] = v;     // coalesced store
        s += v * v;
    }
    g_sqsrc[n] = s;
}

// Prep: transpose target to k-major + c[m] = ||y||^2 - psi
__global__ void prep_tgt_kernel(const float* __restrict__ tgt,
                                const float* __restrict__ psi) {
    int m = blockIdx.x * blockDim.x + threadIdx.x;
    if (m >= M_TGT) return;
    float s = 0.f;
#pragma unroll
    for (int d = 0; d < D_DIM; d++) {
        float v = tgt[m * D_DIM + d];
        g_tgtT[d * M_TGT + m] = v;     // coalesced store
        s += v * v;
    }
    g_c[m] = s - psi[m];
}

// Prep: mean(psi), one block
__global__ void mean_psi_kernel(const float* __restrict__ psi) {
    __shared__ float red[32];
    float s = 0.f;
    for (int i = threadIdx.x; i < M_TGT; i += blockDim.x) s += psi[i];
#pragma unroll
    for (int o = 16; o > 0; o >>= 1) s += __shfl_xor_sync(0xffffffffu, s, o);
    if ((threadIdx.x & 31) == 0) red[threadIdx.x >> 5] = s;
    __syncthreads();
    if (threadIdx.x < 32) {
        int nw = blockDim.x >> 5;
        float v = (threadIdx.x < nw) ? red[threadIdx.x] : 0.f;
#pragma unroll
        for (int o = 16; o > 0; o >>= 1) v += __shfl_xor_sync(0xffffffffu, v, o);
        if (threadIdx.x == 0) g_meanpsi = v * (1.0f / (float)M_TGT);
    }
}

// ---------------------------------------------------------
// Main fused GEMM + row-min kernel.
// grid = (N_SRC/BN, MSPLIT); block = 256 threads.
// Each thread owns an 8x8 micro-tile; A tile in SMEM (k-major),
// B streamed k-major from global (L2/L1 resident, 16x reuse in CTA).
// ---------------------------------------------------------
__global__ void __launch_bounds__(THREADS)
sdot_min_kernel() {
    __shared__ float As[D_DIM][BN];   // 32 KB, k-major
    const int n0 = blockIdx.x * BN;
    const int m0 = blockIdx.y * M_PER_SPLIT;
    const int tid = threadIdx.x;
    const int r = tid >> 4;           // 0..15 : row group (8 rows each)
    const int c = tid & 15;           // 0..15 : col group (8 cols each)

    // Load A tile: coalesced global (g_srcT is k-major), conflict-free SMEM store
#pragma unroll
    for (int i = 0; i < (D_DIM * BN) / THREADS; i++) {   // 32 iters
        int idx = i * THREADS + tid;
        int d = idx >> 7;             // / BN
        int n = idx & (BN - 1);
        As[d][n] = g_srcT[d * N_SRC + n0 + n];
    }
    __syncthreads();

    float minv[TN];
#pragma unroll
    for (int i = 0; i < TN; i++) minv[i] = CUDART_INF_F;

    for (int mt = 0; mt < M_PER_SPLIT; mt += BM) {
        const int mbase = m0 + mt;

        float acc[TN][TM];
#pragma unroll
        for (int i = 0; i < TN; i++)
#pragma unroll
            for (int j = 0; j < TM; j++) acc[i][j] = 0.f;

#pragma unroll 4
        for (int k = 0; k < D_DIM; k++) {
            float a[TN], b[TM];
            // A fragment from SMEM (vectorized, broadcast-friendly)
            float4 a0 = *reinterpret_cast<const float4*>(&As[k][r * TN]);
            float4 a1 = *reinterpret_cast<const float4*>(&As[k][r * TN + 4]);
            a[0] = a0.x; a[1] = a0.y; a[2] = a0.z; a[3] = a0.w;
            a[4] = a1.x; a[5] = a1.y; a[6] = a1.z; a[7] = a1.w;
            // B fragment straight from global (k-major; L1/L2 hits)
            const float* bp = &g_tgtT[k * M_TGT + mbase + c * TM];
            float4 b0 = *reinterpret_cast<const float4*>(bp);
            float4 b1 = *reinterpret_cast<const float4*>(bp + 4);
            b[0] = b0.x; b[1] = b0.y; b[2] = b0.z; b[3] = b0.w;
            b[4] = b1.x; b[5] = b1.y; b[6] = b1.z; b[7] = b1.w;
#pragma unroll
            for (int i = 0; i < TN; i++)
#pragma unroll
                for (int j = 0; j < TM; j++)
                    acc[i][j] = fmaf(a[i], b[j], acc[i][j]);
        }

        // Fold this tile into the running min: val = c[m] - 2*dot
        const float* cp = &g_c[mbase + c * TM];
        float4 c0 = *reinterpret_cast<const float4*>(cp);
        float4 c1 = *reinterpret_cast<const float4*>(cp + 4);
        float cc[TM] = {c0.x, c0.y, c0.z, c0.w, c1.x, c1.y, c1.z, c1.w};
#pragma unroll
        for (int i = 0; i < TN; i++) {
#pragma unroll
            for (int j = 0; j < TM; j++) {
                float v = fmaf(-2.0f, acc[i][j], cc[j]);
                minv[i] = fminf(minv[i], v);
            }
        }
    }

    // Reduce min across the 16 col-group threads (lanes (r&1)*16 + c)
#pragma unroll
    for (int i = 0; i < TN; i++) {
        float v = minv[i];
#pragma unroll
        for (int off = 1; off < 16; off <<= 1)
            v = fminf(v, __shfl_xor_sync(0xffffffffu, v, off));
        if (c == 0)
            g_partial[(n0 + r * TN + i) * MSPLIT + blockIdx.y] = v;
    }
}

// ---------------------------------------------------------
// Finalize: min over splits + ||x||^2 + mean(psi)
// ---------------------------------------------------------
__global__ void finalize_kernel(float* __restrict__ out) {
    int n = blockIdx.x * blockDim.x + threadIdx.x;
    if (n >= N_SRC) return;
    float v = CUDART_INF_F;
#pragma unroll
    for (int s = 0; s < MSPLIT; s++)
        v = fminf(v, g_partial[n * MSPLIT + s]);
    out[n] = v + g_sqsrc[n] + g_meanpsi;
}

// ---------------------------------------------------------
extern "C" void kernel_launch(void* const* d_in, const int* in_sizes, int n_in,
                              void* d_out, int out_size) {
    const float* src = (const float*)d_in[0];   // [8192, 64]
    const float* tgt = (const float*)d_in[1];   // [32768, 64]
    const float* psi = (const float*)d_in[2];   // [32768]
    float* out = (float*)d_out;                 // [8192]

    prep_src_kernel<<<N_SRC / 256, 256>>>(src);
    prep_tgt_kernel<<<M_TGT / 256, 256>>>(tgt, psi);
    mean_psi_kernel<<<1, 1024>>>(psi);

    dim3 grid(N_SRC / BN, MSPLIT);
    sdot_min_kernel<<<grid, THREADS>>>();

    finalize_kernel<<<N_SRC / 256, 256>>>(out);
}

// round 3
// speedup vs baseline: 9.6443x; 9.6443x over previous
#include <cuda_runtime.h>
#include <cuda_fp16.h>
#include <math_constants.h>
#include <cstdint>

// ----------------------- problem constants -----------------------
#define N_SRC 8192
#define M_TGT 32768
#define D_DIM 64
#define BN 128                      // src rows per tile (CTA M)
#define BM 128                      // tgt rows per chunk (CTA N)
#define NTILES (N_SRC / BN)         // 64
#define MCHUNKS (M_TGT / BM)        // 256
#define NUNITS (NTILES * MCHUNKS)   // 16384
#define NCTAS 148
#define THREADS 256

// ----------------------- SMEM layout -----------------------------
#define SM_A    0                   // 128 x 128B = 16384
#define SM_B    16384               // 2 x 16384
#define SM_C    49152               // 2 x 512B (128 floats per stage)
#define SM_MIN  50176               // 256 floats
#define SMEM_TOTAL 51200

// ----------------------- device scratch --------------------------
__device__ __half g_src_h[N_SRC * D_DIM];   // fp16 source, row-major
__device__ __half g_tgt_h[M_TGT * D_DIM];   // fp16 target, row-major
__device__ float  g_c[M_TGT];               // ||y_m||^2 - psi[m]
__device__ float  g_sqsrc[N_SRC];           // ||x_n||^2
__device__ float  g_meanpsi;
__device__ int    g_partial[N_SRC];         // float bits, atomic-min'd

// ----------------------- helpers ---------------------------------
__device__ __forceinline__ uint32_t smem_u32(const void* p) {
    uint32_t a;
    asm("{ .reg .u64 t; cvta.to.shared.u64 t, %1; cvt.u32.u64 %0, t; }" : "=r"(a) : "l"(p));
    return a;
}
__device__ __forceinline__ uint32_t swz128(uint32_t off) { return off ^ ((off >> 3) & 0x70); }

#define CP_ASYNC16(dst, src) \
    asm volatile("cp.async.cg.shared.global [%0], [%1], 16;" :: "r"((uint32_t)(dst)), "l"(src) : "memory")
#define CP_COMMIT() asm volatile("cp.async.commit_group;" ::: "memory")
#define CP_WAIT0()  asm volatile("cp.async.wait_group 0;" ::: "memory")

#define LDSM_X4(r0, r1, r2, r3, addr) \
    asm volatile("ldmatrix.sync.aligned.m8n8.x4.shared.b16 {%0,%1,%2,%3}, [%4];" \
                 : "=r"(r0), "=r"(r1), "=r"(r2), "=r"(r3) : "r"(addr))

#define MMA16816(d, a, b0, b1) \
    asm volatile("mma.sync.aligned.m16n8k16.row.col.f32.f16.f16.f32 " \
                 "{%0,%1,%2,%3},{%4,%5,%6,%7},{%8,%9},{%0,%1,%2,%3};" \
                 : "+f"((d)[0]), "+f"((d)[1]), "+f"((d)[2]), "+f"((d)[3]) \
                 : "r"((a)[0]), "r"((a)[1]), "r"((a)[2]), "r"((a)[3]), "r"(b0), "r"(b1))

// Order-preserving float atomic-min on an int cell initialized to +inf bits.
__device__ __forceinline__ void atomicMinF(int* addr, float v) {
    if (v >= 0.f) atomicMin(addr, __float_as_int(v));
    else          atomicMax((unsigned int*)addr, __float_as_uint(v));
}

// ----------------------- prep kernels ----------------------------
__global__ void convert_kernel(const float* __restrict__ src, const float* __restrict__ tgt) {
    int i = blockIdx.x * blockDim.x + threadIdx.x;
    const int TS = N_SRC * D_DIM / 2, TT = M_TGT * D_DIM / 2;
    if (i < TS) {
        float2 v = reinterpret_cast<const float2*>(src)[i];
        reinterpret_cast<__half2*>(g_src_h)[i] = __floats2half2_rn(v.x, v.y);
    }
    if (i < TT) {
        float2 v = reinterpret_cast<const float2*>(tgt)[i];
        reinterpret_cast<__half2*>(g_tgt_h)[i] = __floats2half2_rn(v.x, v.y);
    }
}

__global__ void norms_kernel(const float* __restrict__ src, const float* __restrict__ tgt,
                             const float* __restrict__ psi) {
    int gw = (blockIdx.x * blockDim.x + threadIdx.x) >> 5;
    int lane = threadIdx.x & 31;
    if (gw < N_SRC) {
        float2 a = reinterpret_cast<const float2*>(src + (size_t)gw * D_DIM)[lane];
        float s = a.x * a.x + a.y * a.y;
#pragma unroll
        for (int o = 16; o > 0; o >>= 1) s += __shfl_xor_sync(0xffffffffu, s, o);
        if (lane == 0) g_sqsrc[gw] = s;
    } else if (gw < N_SRC + M_TGT) {
        int m = gw - N_SRC;
        float2 a = reinterpret_cast<const float2*>(tgt + (size_t)m * D_DIM)[lane];
        float s = a.x * a.x + a.y * a.y;
#pragma unroll
        for (int o = 16; o > 0; o >>= 1) s += __shfl_xor_sync(0xffffffffu, s, o);
        if (lane == 0) g_c[m] = s - psi[m];
    }
}

__global__ void mean_psi_init_kernel(const float* __restrict__ psi) {
    // blockIdx 0: mean(psi); others: init g_partial to +inf bits
    if (blockIdx.x == 0) {
        __shared__ float red[32];
        float s = 0.f;
        for (int i = threadIdx.x; i < M_TGT; i += blockDim.x) s += psi[i];
#pragma unroll
        for (int o = 16; o > 0; o >>= 1) s += __shfl_xor_sync(0xffffffffu, s, o);
        if ((threadIdx.x & 31) == 0) red[threadIdx.x >> 5] = s;
        __syncthreads();
        if (threadIdx.x < 32) {
            float v = (threadIdx.x < (blockDim.x >> 5)) ? red[threadIdx.x] : 0.f;
#pragma unroll
            for (int o = 16; o > 0; o >>= 1) v += __shfl_xor_sync(0xffffffffu, v, o);
            if (threadIdx.x == 0) g_meanpsi = v * (1.0f / (float)M_TGT);
        }
    } else {
        int n = (blockIdx.x - 1) * blockDim.x + threadIdx.x;
        if (n < N_SRC) g_partial[n] = 0x7F800000;   // +inf
    }
}

// ----------------------- main HMMA kernel ------------------------
__device__ __forceinline__ void load_B_chunk(uint32_t sb, int stage, int ch, int tid) {
    const __half* p = g_tgt_h + (size_t)ch * BM * D_DIM;
    uint32_t d = sb + SM_B + stage * 16384;
#pragma unroll
    for (int j = 0; j < 4; j++) {
        int idx = j * THREADS + tid;
        int row = idx >> 3, c8 = idx & 7;
        CP_ASYNC16(d + swz128(row * 128 + c8 * 16), p + row * D_DIM + c8 * 8);
    }
    if (tid < 32)
        CP_ASYNC16(sb + SM_C + stage * 512 + tid * 16, g_c + (size_t)ch * BM + tid * 4);
}

__device__ __forceinline__ void load_A_tile(uint32_t sb, int nt, int tid) {
    const __half* p = g_src_h + (size_t)nt * BN * D_DIM;
#pragma unroll
    for (int j = 0; j < 4; j++) {
        int idx = j * THREADS + tid;
        int row = idx >> 3, c8 = idx & 7;
        CP_ASYNC16(sb + SM_A + swz128(row * 128 + c8 * 16), p + row * D_DIM + c8 * 8);
    }
}

__device__ __forceinline__ void load_A_frags(uint32_t sb, int wm, int lane, uint32_t a[2][4][4]) {
#pragma unroll
    for (int mt = 0; mt < 2; mt++)
#pragma unroll
        for (int ks = 0; ks < 4; ks++) {
            uint32_t row = wm * 32 + mt * 16 + (lane & 15);
            uint32_t kb = ks * 32 + ((lane >> 4) & 1) * 16;
            uint32_t addr = sb + SM_A + swz128(row * 128 + kb);
            LDSM_X4(a[mt][ks][0], a[mt][ks][1], a[mt][ks][2], a[mt][ks][3], addr);
        }
}

__device__ __forceinline__ void flush_mins(char* smem, float minv[2][2],
                                           int n0, int wm, int wn, int q, int e, int tid) {
    float* smin = reinterpret_cast<float*>(smem + SM_MIN);
#pragma unroll
    for (int mt = 0; mt < 2; mt++)
#pragma unroll
        for (int h = 0; h < 2; h++) {
            float v = minv[mt][h];
            v = fminf(v, __shfl_xor_sync(0xffffffffu, v, 1));
            v = fminf(v, __shfl_xor_sync(0xffffffffu, v, 2));
            if (e == 0) smin[wn * 128 + wm * 32 + mt * 16 + h * 8 + q] = v;
        }
    __syncthreads();
    if (tid < 128) {
        float v = fminf(smin[tid], smin[128 + tid]);
        atomicMinF(&g_partial[n0 + tid], v);
    }
    __syncthreads();
}

__global__ void __launch_bounds__(THREADS, 1) sdot_hmma_kernel() {
    extern __shared__ char smem[];
    uint32_t sb = smem_u32(smem);
    const int tid = threadIdx.x, wid = tid >> 5, lane = tid & 31;
    const int wm = wid & 3, wn = wid >> 2;    // warp tile: rows wm*32+[0,32), cols wn*64+[0,64)
    const int q = lane >> 2, e = lane & 3;

    const int cta = blockIdx.x;
    const int us = (int)(((long long)cta * NUNITS) / NCTAS);
    const int ue = (int)(((long long)(cta + 1) * NUNITS) / NCTAS);

    float minv[2][2] = {{CUDART_INF_F, CUDART_INF_F}, {CUDART_INF_F, CUDART_INF_F}};
    uint32_t a[2][4][4];
    int cur_nt = -1;

    // prologue: B/c for first unit into stage 0 (waited inside first A reload)
    load_B_chunk(sb, 0, us & (MCHUNKS - 1), tid);
    CP_COMMIT();

    for (int u = us; u < ue; ++u) {
        const int nt = u >> 8;                  // MCHUNKS = 256
        const int stage = (u - us) & 1;

        if (nt != cur_nt) {
            if (cur_nt >= 0) {
                flush_mins(smem, minv, cur_nt * BN, wm, wn, q, e, tid);
#pragma unroll
                for (int mt = 0; mt < 2; mt++) { minv[mt][0] = CUDART_INF_F; minv[mt][1] = CUDART_INF_F; }
            }
            load_A_tile(sb, nt, tid);
            CP_COMMIT();
            CP_WAIT0();                          // completes A (and any pending B)
            __syncthreads();
            load_A_frags(sb, wm, lane, a);
            cur_nt = nt;
        }

        if (u + 1 < ue) {
            load_B_chunk(sb, stage ^ 1, (u + 1) & (MCHUNKS - 1), tid);
            CP_COMMIT();
        }

        // ---- compute 128x128 tile from B[stage], A in regs ----
        const uint32_t bbase = sb + SM_B + stage * 16384;
        const float2* cb2 = reinterpret_cast<const float2*>(smem + SM_C + stage * 512);
#pragma unroll
        for (int ntile = 0; ntile < 8; ntile++) {
            uint32_t b0[4], b1[4];
            uint32_t nrow = wn * 64 + ntile * 8 + (lane & 7);
            uint32_t kb = (lane >> 3) * 16;
            LDSM_X4(b0[0], b0[1], b0[2], b0[3], bbase + swz128(nrow * 128 + kb));
            LDSM_X4(b1[0], b1[1], b1[2], b1[3], bbase + swz128(nrow * 128 + 64 + kb));

            float d0[4] = {0.f, 0.f, 0.f, 0.f};
            float d1[4] = {0.f, 0.f, 0.f, 0.f};
            MMA16816(d0, a[0][0], b0[0], b0[1]);
            MMA16816(d1, a[1][0], b0[0], b0[1]);
            MMA16816(d0, a[0][1], b0[2], b0[3]);
            MMA16816(d1, a[1][1], b0[2], b0[3]);
            MMA16816(d0, a[0][2], b1[0], b1[1]);
            MMA16816(d1, a[1][2], b1[0], b1[1]);
            MMA16816(d0, a[0][3], b1[2], b1[3]);
            MMA16816(d1, a[1][3], b1[2], b1[3]);

            float2 cb = cb2[wn * 32 + ntile * 4 + e];
            minv[0][0] = fminf(minv[0][0], fminf(fmaf(-2.f, d0[0], cb.x), fmaf(-2.f, d0[1], cb.y)));
            minv[0][1] = fminf(minv[0][1], fminf(fmaf(-2.f, d0[2], cb.x), fmaf(-2.f, d0[3], cb.y)));
            minv[1][0] = fminf(minv[1][0], fminf(fmaf(-2.f, d1[0], cb.x), fmaf(-2.f, d1[1], cb.y)));
            minv[1][1] = fminf(minv[1][1], fminf(fmaf(-2.f, d1[2], cb.x), fmaf(-2.f, d1[3], cb.y)));
        }

        if (u + 1 < ue) CP_WAIT0();
        __syncthreads();
    }

    flush_mins(smem, minv, cur_nt * BN, wm, wn, q, e, tid);
}

// ----------------------- finalize --------------------------------
__global__ void finalize_kernel(float* __restrict__ out) {
    int n = blockIdx.x * blockDim.x + threadIdx.x;
    if (n >= N_SRC) return;
    out[n] = __int_as_float(g_partial[n]) + g_sqsrc[n] + g_meanpsi;
}

// ----------------------- launch ----------------------------------
extern "C" void kernel_launch(void* const* d_in, const int* in_sizes, int n_in,
                              void* d_out, int out_size) {
    const float* src = (const float*)d_in[0];   // [8192, 64]
    const float* tgt = (const float*)d_in[1];   // [32768, 64]
    const float* psi = (const float*)d_in[2];   // [32768]
    float* out = (float*)d_out;                 // [8192]

    cudaFuncSetAttribute(sdot_hmma_kernel, cudaFuncAttributeMaxDynamicSharedMemorySize, SMEM_TOTAL);

    {
        int total = M_TGT * D_DIM / 2;
        convert_kernel<<<(total + 255) / 256, 256>>>(src, tgt);
    }
    {
        int warps = N_SRC + M_TGT;
        norms_kernel<<<(warps * 32 + 255) / 256, 256>>>(src, tgt, psi);
    }
    mean_psi_init_kernel<<<1 + (N_SRC + 1023) / 1024, 1024>>>(psi);

    sdot_hmma_kernel<<<NCTAS, THREADS, SMEM_TOTAL>>>();

    finalize_kernel<<<(N_SRC + 255) / 256, 256>>>(out);
}

// round 4
// speedup vs baseline: 10.3245x; 1.0705x over previous
#include <cuda_runtime.h>
#include <cuda_fp16.h>
#include <math_constants.h>
#include <cstdint>

// ----------------------- problem constants -----------------------
#define N_SRC 8192
#define M_TGT 32768
#define D_DIM 64
#define BN 128                      // src rows per tile (CTA M)
#define BM 128                      // tgt rows per chunk (CTA N)
#define NTILES (N_SRC / BN)         // 64
#define MCHUNKS (M_TGT / BM)        // 256
#define NUNITS (NTILES * MCHUNKS)   // 16384
#define NCTAS 148
#define THREADS 512                 // 16 warps, 4 per SMSP

// ----------------------- SMEM layout -----------------------------
#define SM_A    0                   // 128 x 128B = 16384
#define SM_B    16384               // 2 x 16384
#define SM_C    49152               // 2 x 512B (128 floats per stage)
#define SM_MIN  50176               // 512 floats (2KB)
#define SMEM_TOTAL 52224

// ----------------------- device scratch --------------------------
__device__ __half g_src_h[N_SRC * D_DIM];   // fp16 source, row-major
__device__ __half g_tgt_h[M_TGT * D_DIM];   // fp16 target, row-major
__device__ float  g_c[M_TGT];               // ||y_m||^2 - psi[m]
__device__ float  g_sqsrc[N_SRC];           // ||x_n||^2
__device__ float  g_meanpsi;
__device__ int    g_partial[N_SRC];         // float bits, atomic-min'd

// ----------------------- helpers ---------------------------------
__device__ __forceinline__ uint32_t smem_u32(const void* p) {
    uint32_t a;
    asm("{ .reg .u64 t; cvta.to.shared.u64 t, %1; cvt.u32.u64 %0, t; }" : "=r"(a) : "l"(p));
    return a;
}
__device__ __forceinline__ uint32_t swz128(uint32_t off) { return off ^ ((off >> 3) & 0x70); }

#define CP_ASYNC16(dst, src) \
    asm volatile("cp.async.cg.shared.global [%0], [%1], 16;" :: "r"((uint32_t)(dst)), "l"(src) : "memory")
#define CP_COMMIT() asm volatile("cp.async.commit_group;" ::: "memory")
#define CP_WAIT0()  asm volatile("cp.async.wait_group 0;" ::: "memory")

#define LDSM_X4(r0, r1, r2, r3, addr) \
    asm volatile("ldmatrix.sync.aligned.m8n8.x4.shared.b16 {%0,%1,%2,%3}, [%4];" \
                 : "=r"(r0), "=r"(r1), "=r"(r2), "=r"(r3) : "r"(addr))

#define MMA16816(d, a, b0, b1) \
    asm volatile("mma.sync.aligned.m16n8k16.row.col.f32.f16.f16.f32 " \
                 "{%0,%1,%2,%3},{%4,%5,%6,%7},{%8,%9},{%0,%1,%2,%3};" \
                 : "+f"((d)[0]), "+f"((d)[1]), "+f"((d)[2]), "+f"((d)[3]) \
                 : "r"((a)[0]), "r"((a)[1]), "r"((a)[2]), "r"((a)[3]), "r"(b0), "r"(b1))

// Order-preserving float atomic-min on an int cell initialized to +inf bits.
__device__ __forceinline__ void atomicMinF(int* addr, float v) {
    if (v >= 0.f) atomicMin(addr, __float_as_int(v));
    else          atomicMax((unsigned int*)addr, __float_as_uint(v));
}

// ----------------------- fused prep: fp16 convert + norms + c ----
// One warp per row of src (first N_SRC warps) or tgt (next M_TGT warps).
__global__ void prep_kernel(const float* __restrict__ src, const float* __restrict__ tgt,
                            const float* __restrict__ psi) {
    int gw = (blockIdx.x * blockDim.x + threadIdx.x) >> 5;
    int lane = threadIdx.x & 31;
    if (gw < N_SRC) {
        float2 a = reinterpret_cast<const float2*>(src + (size_t)gw * D_DIM)[lane];
        reinterpret_cast<__half2*>(g_src_h + (size_t)gw * D_DIM)[lane] = __floats2half2_rn(a.x, a.y);
        float s = a.x * a.x + a.y * a.y;
#pragma unroll
        for (int o = 16; o > 0; o >>= 1) s += __shfl_xor_sync(0xffffffffu, s, o);
        if (lane == 0) g_sqsrc[gw] = s;
    } else if (gw < N_SRC + M_TGT) {
        int m = gw - N_SRC;
        float2 a = reinterpret_cast<const float2*>(tgt + (size_t)m * D_DIM)[lane];
        reinterpret_cast<__half2*>(g_tgt_h + (size_t)m * D_DIM)[lane] = __floats2half2_rn(a.x, a.y);
        float s = a.x * a.x + a.y * a.y;
#pragma unroll
        for (int o = 16; o > 0; o >>= 1) s += __shfl_xor_sync(0xffffffffu, s, o);
        if (lane == 0) g_c[m] = s - psi[m];
    }
}

__global__ void mean_psi_init_kernel(const float* __restrict__ psi) {
    if (blockIdx.x == 0) {
        __shared__ float red[32];
        float s = 0.f;
        for (int i = threadIdx.x; i < M_TGT; i += blockDim.x) s += psi[i];
#pragma unroll
        for (int o = 16; o > 0; o >>= 1) s += __shfl_xor_sync(0xffffffffu, s, o);
        if ((threadIdx.x & 31) == 0) red[threadIdx.x >> 5] = s;
        __syncthreads();
        if (threadIdx.x < 32) {
            float v = (threadIdx.x < (blockDim.x >> 5)) ? red[threadIdx.x] : 0.f;
#pragma unroll
            for (int o = 16; o > 0; o >>= 1) v += __shfl_xor_sync(0xffffffffu, v, o);
            if (threadIdx.x == 0) g_meanpsi = v * (1.0f / (float)M_TGT);
        }
    } else {
        int n = (blockIdx.x - 1) * blockDim.x + threadIdx.x;
        if (n < N_SRC) g_partial[n] = 0x7F800000;   // +inf
    }
}

// ----------------------- main HMMA kernel ------------------------
__device__ __forceinline__ void load_B_chunk(uint32_t sb, int stage, int ch, int tid) {
    const __half* p = g_tgt_h + (size_t)ch * BM * D_DIM;
    uint32_t d = sb + SM_B + stage * 16384;
#pragma unroll
    for (int j = 0; j < 2; j++) {
        int idx = j * THREADS + tid;
        int row = idx >> 3, c8 = idx & 7;
        CP_ASYNC16(d + swz128(row * 128 + c8 * 16), p + row * D_DIM + c8 * 8);
    }
    if (tid < 32)
        CP_ASYNC16(sb + SM_C + stage * 512 + tid * 16, g_c + (size_t)ch * BM + tid * 4);
}

__device__ __forceinline__ void load_A_tile(uint32_t sb, int nt, int tid) {
    const __half* p = g_src_h + (size_t)nt * BN * D_DIM;
#pragma unroll
    for (int j = 0; j < 2; j++) {
        int idx = j * THREADS + tid;
        int row = idx >> 3, c8 = idx & 7;
        CP_ASYNC16(sb + SM_A + swz128(row * 128 + c8 * 16), p + row * D_DIM + c8 * 8);
    }
}

__device__ __forceinline__ void load_A_frags(uint32_t sb, int wm, int lane, uint32_t a[2][4][4]) {
#pragma unroll
    for (int mt = 0; mt < 2; mt++)
#pragma unroll
        for (int ks = 0; ks < 4; ks++) {
            uint32_t row = wm * 32 + mt * 16 + (lane & 15);
            uint32_t kb = ks * 32 + ((lane >> 4) & 1) * 16;
            uint32_t addr = sb + SM_A + swz128(row * 128 + kb);
            LDSM_X4(a[mt][ks][0], a[mt][ks][1], a[mt][ks][2], a[mt][ks][3], addr);
        }
}

__device__ __forceinline__ void flush_mins(char* smem, float minv[2][2],
                                           int n0, int wm, int wn, int q, int e, int tid) {
    float* smin = reinterpret_cast<float*>(smem + SM_MIN);
#pragma unroll
    for (int mt = 0; mt < 2; mt++)
#pragma unroll
        for (int h = 0; h < 2; h++) {
            float v = minv[mt][h];
            v = fminf(v, __shfl_xor_sync(0xffffffffu, v, 1));
            v = fminf(v, __shfl_xor_sync(0xffffffffu, v, 2));
            if (e == 0) smin[wn * 128 + wm * 32 + mt * 16 + h * 8 + q] = v;
        }
    __syncthreads();
    if (tid < 128) {
        const float* s0 = smin;
        float v = fminf(fminf(s0[tid], s0[128 + tid]), fminf(s0[256 + tid], s0[384 + tid]));
        atomicMinF(&g_partial[n0 + tid], v);
    }
    __syncthreads();
}

__global__ void __launch_bounds__(THREADS, 1) sdot_hmma_kernel() {
    extern __shared__ char smem[];
    uint32_t sb = smem_u32(smem);
    const int tid = threadIdx.x, wid = tid >> 5, lane = tid & 31;
    const int wm = wid & 3, wn = wid >> 2;    // warp tile: rows wm*32+[0,32), cols wn*32+[0,32)
    const int q = lane >> 2, e = lane & 3;

    const int cta = blockIdx.x;
    const int us = (int)(((long long)cta * NUNITS) / NCTAS);
    const int ue = (int)(((long long)(cta + 1) * NUNITS) / NCTAS);

    float minv[2][2] = {{CUDART_INF_F, CUDART_INF_F}, {CUDART_INF_F, CUDART_INF_F}};
    uint32_t a[2][4][4];
    int cur_nt = -1;

    load_B_chunk(sb, 0, us & (MCHUNKS - 1), tid);
    CP_COMMIT();

    for (int u = us; u < ue; ++u) {
        const int nt = u >> 8;                  // MCHUNKS = 256
        const int stage = (u - us) & 1;

        if (nt != cur_nt) {
            if (cur_nt >= 0) {
                flush_mins(smem, minv, cur_nt * BN, wm, wn, q, e, tid);
#pragma unroll
                for (int mt = 0; mt < 2; mt++) { minv[mt][0] = CUDART_INF_F; minv[mt][1] = CUDART_INF_F; }
            }
            load_A_tile(sb, nt, tid);
            CP_COMMIT();
            CP_WAIT0();
            __syncthreads();
            load_A_frags(sb, wm, lane, a);
            cur_nt = nt;
        }

        if (u + 1 < ue) {
            load_B_chunk(sb, stage ^ 1, (u + 1) & (MCHUNKS - 1), tid);
            CP_COMMIT();
        }

        // ---- compute: warp covers rows wm*32+[0,32), cols wn*32+[0,32) ----
        const uint32_t bbase = sb + SM_B + stage * 16384;
        const float2* cb2 = reinterpret_cast<const float2*>(smem + SM_C + stage * 512);
#pragma unroll
        for (int ntile = 0; ntile < 4; ntile++) {
            uint32_t b0[4], b1[4];
            uint32_t nrow = wn * 32 + ntile * 8 + (lane & 7);
            uint32_t kb = (lane >> 3) * 16;
            LDSM_X4(b0[0], b0[1], b0[2], b0[3], bbase + swz128(nrow * 128 + kb));
            LDSM_X4(b1[0], b1[1], b1[2], b1[3], bbase + swz128(nrow * 128 + 64 + kb));

            float d0[4] = {0.f, 0.f, 0.f, 0.f};
            float d1[4] = {0.f, 0.f, 0.f, 0.f};
            MMA16816(d0, a[0][0], b0[0], b0[1]);
            MMA16816(d1, a[1][0], b0[0], b0[1]);
            MMA16816(d0, a[0][1], b0[2], b0[3]);
            MMA16816(d1, a[1][1], b0[2], b0[3]);
            MMA16816(d0, a[0][2], b1[0], b1[1]);
            MMA16816(d1, a[1][2], b1[0], b1[1]);
            MMA16816(d0, a[0][3], b1[2], b1[3]);
            MMA16816(d1, a[1][3], b1[2], b1[3]);

            float2 cb = cb2[wn * 16 + ntile * 4 + e];
            minv[0][0] = fminf(minv[0][0], fminf(fmaf(-2.f, d0[0], cb.x), fmaf(-2.f, d0[1], cb.y)));
            minv[0][1] = fminf(minv[0][1], fminf(fmaf(-2.f, d0[2], cb.x), fmaf(-2.f, d0[3], cb.y)));
            minv[1][0] = fminf(minv[1][0], fminf(fmaf(-2.f, d1[0], cb.x), fmaf(-2.f, d1[1], cb.y)));
            minv[1][1] = fminf(minv[1][1], fminf(fmaf(-2.f, d1[2], cb.x), fmaf(-2.f, d1[3], cb.y)));
        }

        if (u + 1 < ue) CP_WAIT0();
        __syncthreads();
    }

    flush_mins(smem, minv, cur_nt * BN, wm, wn, q, e, tid);
}

// ----------------------- finalize --------------------------------
__global__ void finalize_kernel(float* __restrict__ out) {
    int n = blockIdx.x * blockDim.x + threadIdx.x;
    if (n >= N_SRC) return;
    out[n] = __int_as_float(g_partial[n]) + g_sqsrc[n] + g_meanpsi;
}

// ----------------------- launch ----------------------------------
extern "C" void kernel_launch(void* const* d_in, const int* in_sizes, int n_in,
                              void* d_out, int out_size) {
    const float* src = (const float*)d_in[0];   // [8192, 64]
    const float* tgt = (const float*)d_in[1];   // [32768, 64]
    const float* psi = (const float*)d_in[2];   // [32768]
    float* out = (float*)d_out;                 // [8192]

    cudaFuncSetAttribute(sdot_hmma_kernel, cudaFuncAttributeMaxDynamicSharedMemorySize, SMEM_TOTAL);

    {
        int warps = N_SRC + M_TGT;
        prep_kernel<<<(warps * 32 + 255) / 256, 256>>>(src, tgt, psi);
    }
    mean_psi_init_kernel<<<1 + (N_SRC + 1023) / 1024, 1024>>>(psi);

    sdot_hmma_kernel<<<NCTAS, THREADS, SMEM_TOTAL>>>();

    finalize_kernel<<<(N_SRC + 255) / 256, 256>>>(out);
}